// round 14
// baseline (speedup 1.0000x reference)
#include <cuda_runtime.h>
#include <cstdint>

// Problem constants (from reference)
#define NTOKENS    8192
#define TOPK       2
#define HIDDEN     4096
#define NUM_GROUPS 2
#define M_FULL     (NTOKENS * TOPK)   // 16384

#define CHUNK_F4    32                         // float4 per chunk = 512 B
#define ROW_F4      (HIDDEN / 4)               // 1024 float4 per row
#define NCHUNK      (ROW_F4 / CHUNK_F4)        // 32 chunks
#define TOK_PER_WARP 2
#define TOK_PER_CTA  (8 * TOK_PER_WARP)        // 8 warps x 2 tokens = 16

// ---------------------------------------------------------------------------
// Single fused kernel: out[t,:] = buf[0,i0,:]+buf[0,i1,:]+buf[1,i0,:]+buf[1,i1,:]
//
//   grid = (NTOKENS/16, NCHUNK), block = 256 (8 warps).
//   Warp w of block (x, c) handles tokens t0 = x*16 + w*2 and t0+1, for the
//   512B column chunk c. Per thread: 8 independent LDG.128 in flight (4 rows
//   x 2 tokens) -> double the MLP of the one-token version, and the per-warp
//   prologue (dtype probe, REDUX, index fetch) is amortized over 2 tokens.
//
//   Index dtype detection (per warp, branchless): odd int32 words of the
//   index buffer are all-zero iff dtype is int64 (values < 16384). All lanes
//   read the same 128B (L1 broadcast), REDUX.OR decides. Both dtype views of
//   the two tokens' indices are loaded up-front (int4 = both tokens' int32
//   view in ONE LDG.128; two longlong2 for the int64 view); SELs resolve.
//   All reads in-bounds for either dtype (int32 buffer = 128KB exactly).
//
//   Chunk-major scheduling: for fixed chunk c the source slice is
//   2 groups x 16384 rows x 512B = 16MB (~10.4MB distinct) -> L2-resident,
//   duplicate-index rows hit L2 (traffic at the ~449MB dedup floor,
//   confirmed by ncu in R12/R13). __stcs keeps the 128MB write stream from
//   evicting the slab.
// ---------------------------------------------------------------------------
__global__ __launch_bounds__(256) void k_gather_sum(
    const float* __restrict__ buf,
    const void*  __restrict__ idx,
    float*       __restrict__ out)
{
    const int warp = threadIdx.x >> 5;
    const int lane = threadIdx.x & 31;
    const int t0   = blockIdx.x * TOK_PER_CTA + warp * TOK_PER_WARP;
    const int c    = blockIdx.y;

    // --- dtype detection + index fetch (branchless, all loads independent) ---
    const int       probe = __ldg(&((const int*)idx)[2 * lane + 1]);
    const int4      i32v  = __ldg(&((const int4*)idx)[t0 >> 1]);      // int32 view, both tokens
    const longlong2 l64a  = __ldg(&((const longlong2*)idx)[t0]);      // int64 view, token t0
    const longlong2 l64b  = __ldg(&((const longlong2*)idx)[t0 + 1]);  // int64 view, token t0+1

    const bool is64 = (__reduce_or_sync(0xFFFFFFFFu, probe) == 0);
    const int a0 = is64 ? (int)l64a.x : i32v.x;   // token t0,   topk 0
    const int a1 = is64 ? (int)l64a.y : i32v.y;   // token t0,   topk 1
    const int b0 = is64 ? (int)l64b.x : i32v.z;   // token t0+1, topk 0
    const int b1 = is64 ? (int)l64b.y : i32v.w;   // token t0+1, topk 1

    const float4* __restrict__ b4 = (const float4*)buf;
    const int col = c * CHUNK_F4 + lane;

    // 8 independent LDG.128 in flight
    const float4 va0 = __ldg(&b4[(size_t)a0 * ROW_F4 + col]);
    const float4 va1 = __ldg(&b4[(size_t)a1 * ROW_F4 + col]);
    const float4 va2 = __ldg(&b4[((size_t)M_FULL + a0) * ROW_F4 + col]);
    const float4 va3 = __ldg(&b4[((size_t)M_FULL + a1) * ROW_F4 + col]);
    const float4 vb0 = __ldg(&b4[(size_t)b0 * ROW_F4 + col]);
    const float4 vb1 = __ldg(&b4[(size_t)b1 * ROW_F4 + col]);
    const float4 vb2 = __ldg(&b4[((size_t)M_FULL + b0) * ROW_F4 + col]);
    const float4 vb3 = __ldg(&b4[((size_t)M_FULL + b1) * ROW_F4 + col]);

    float4 sa, sb;
    sa.x = (va0.x + va1.x) + (va2.x + va3.x);
    sa.y = (va0.y + va1.y) + (va2.y + va3.y);
    sa.z = (va0.z + va1.z) + (va2.z + va3.z);
    sa.w = (va0.w + va1.w) + (va2.w + va3.w);
    sb.x = (vb0.x + vb1.x) + (vb2.x + vb3.x);
    sb.y = (vb0.y + vb1.y) + (vb2.y + vb3.y);
    sb.z = (vb0.z + vb1.z) + (vb2.z + vb3.z);
    sb.w = (vb0.w + vb1.w) + (vb2.w + vb3.w);

    __stcs((float4*)out + (size_t)t0 * ROW_F4 + col, sa);
    __stcs((float4*)out + (size_t)(t0 + 1) * ROW_F4 + col, sb);
}

// ---------------------------------------------------------------------------
// Launch contract
//   d_in[0]: gemm_buffer   float32 [NUM_GROUPS, M_FULL, HIDDEN]
//   d_in[1]: scatter_index int32 or int64 [NTOKENS, TOPK] (device-detected)
//   d_out  : float32 [NTOKENS, HIDDEN]
// ---------------------------------------------------------------------------
extern "C" void kernel_launch(void* const* d_in, const int* in_sizes, int n_in,
                              void* d_out, int out_size) {
    const float* buf = (const float*)d_in[0];
    const void*  idx = d_in[1];
    float*       out = (float*)d_out;

    dim3 grid(NTOKENS / TOK_PER_CTA, NCHUNK);   // (512, 32)
    k_gather_sum<<<grid, 256>>>(buf, idx, out);
}

// round 15
// speedup vs baseline: 1.0122x; 1.0122x over previous
#include <cuda_runtime.h>
#include <cstdint>

// Problem constants (from reference)
#define NTOKENS    8192
#define TOPK       2
#define HIDDEN     4096
#define NUM_GROUPS 2
#define M_FULL     (NTOKENS * TOPK)   // 16384

#define ROW_F4      (HIDDEN / 4)               // 1024 float4 per row
#define CHUNK_F4    128                        // float4 per chunk = 2 KB
#define NCHUNK      (ROW_F4 / CHUNK_F4)        // 8 chunks
#define SUB         4                          // 4 x 512B sub-columns per chunk
#define TOK_PER_CTA 8                          // 8 warps -> 8 tokens per CTA

// ---------------------------------------------------------------------------
// Single fused kernel: out[t,:] = buf[0,i0,:]+buf[0,i1,:]+buf[1,i0,:]+buf[1,i1,:]
//
//   grid = (NTOKENS/8, NCHUNK), block = 256 (8 warps).
//   Warp w of block (x, c) handles token t = x*8+w over the 2KB column chunk
//   c (4 x 512B sub-columns; per sub-column each lane does one float4 from
//   each of the 4 source rows).
//
//   WHY 2KB: traffic has been at the ~449MB dedup floor since R12, but
//   achieved BW is stuck at 6.15TB/s vs 6.7TB/s for contiguous streams.
//   First-touch DRAM reads arrive as chunk-sized granules strided 16KB;
//   2KB granules cost 4x fewer DRAM page activations per byte than 512B.
//   Output stores also become 2KB contiguous per (token, chunk).
//
//   L2 slab: for fixed chunk c the source slice is 2x16384x2KB = 64MB
//   (~41MB distinct) -> L2-resident, duplicate-index rows still hit L2.
//   __stcs keeps the 128MB write stream from evicting the slab.
//
//   Index dtype detection (per warp, branchless): odd int32 words of the
//   index buffer are all-zero iff dtype is int64 (values < 16384). All lanes
//   read the same 128B (L1 broadcast); REDUX.OR decides; SELs pick between
//   the two pre-loaded dtype views. All reads in-bounds for either dtype
//   (int32 buffer is exactly 128KB). P(misdetect) = 2^-448.
// ---------------------------------------------------------------------------
__global__ __launch_bounds__(256) void k_gather_sum(
    const float* __restrict__ buf,
    const void*  __restrict__ idx,
    float*       __restrict__ out)
{
    const int warp = threadIdx.x >> 5;
    const int lane = threadIdx.x & 31;
    const int t    = blockIdx.x * TOK_PER_CTA + warp;
    const int c    = blockIdx.y;

    // --- dtype detection + index fetch (branchless, independent loads) ---
    const int       probe = __ldg(&((const int*)idx)[2 * lane + 1]);
    const longlong2 ll    = __ldg(&((const longlong2*)idx)[t]);   // int64 view
    const int2      ii    = __ldg(&((const int2*)idx)[t]);        // int32 view

    const bool is64 = (__reduce_or_sync(0xFFFFFFFFu, probe) == 0);
    const int i0 = is64 ? (int)ll.x : ii.x;
    const int i1 = is64 ? (int)ll.y : ii.y;

    const float4* __restrict__ b4 = (const float4*)buf;
    const size_t r00 = (size_t)i0 * ROW_F4;                  // g0, i0
    const size_t r01 = (size_t)i1 * ROW_F4;                  // g0, i1
    const size_t r10 = ((size_t)M_FULL + i0) * ROW_F4;       // g1, i0
    const size_t r11 = ((size_t)M_FULL + i1) * ROW_F4;       // g1, i1

    const int col0 = c * CHUNK_F4 + lane;
    float4* __restrict__ o4 = (float4*)out + (size_t)t * ROW_F4;

    // 4 sub-columns, processed in 2 batches of 2 (8 loads in flight each)
    #pragma unroll
    for (int h = 0; h < SUB / 2; h++) {
        const int ca = col0 + (2 * h + 0) * 32;
        const int cb = col0 + (2 * h + 1) * 32;

        const float4 a0 = __ldg(&b4[r00 + ca]);
        const float4 a1 = __ldg(&b4[r01 + ca]);
        const float4 a2 = __ldg(&b4[r10 + ca]);
        const float4 a3 = __ldg(&b4[r11 + ca]);
        const float4 b0 = __ldg(&b4[r00 + cb]);
        const float4 b1 = __ldg(&b4[r01 + cb]);
        const float4 b2 = __ldg(&b4[r10 + cb]);
        const float4 b3 = __ldg(&b4[r11 + cb]);

        float4 sa, sb;
        sa.x = (a0.x + a1.x) + (a2.x + a3.x);
        sa.y = (a0.y + a1.y) + (a2.y + a3.y);
        sa.z = (a0.z + a1.z) + (a2.z + a3.z);
        sa.w = (a0.w + a1.w) + (a2.w + a3.w);
        sb.x = (b0.x + b1.x) + (b2.x + b3.x);
        sb.y = (b0.y + b1.y) + (b2.y + b3.y);
        sb.z = (b0.z + b1.z) + (b2.z + b3.z);
        sb.w = (b0.w + b1.w) + (b2.w + b3.w);

        __stcs(&o4[ca], sa);
        __stcs(&o4[cb], sb);
    }
}

// ---------------------------------------------------------------------------
// Launch contract
//   d_in[0]: gemm_buffer   float32 [NUM_GROUPS, M_FULL, HIDDEN]
//   d_in[1]: scatter_index int32 or int64 [NTOKENS, TOPK] (device-detected)
//   d_out  : float32 [NTOKENS, HIDDEN]
// ---------------------------------------------------------------------------
extern "C" void kernel_launch(void* const* d_in, const int* in_sizes, int n_in,
                              void* d_out, int out_size) {
    const float* buf = (const float*)d_in[0];
    const void*  idx = d_in[1];
    float*       out = (float*)d_out;

    dim3 grid(NTOKENS / TOK_PER_CTA, NCHUNK);   // (1024, 8)
    k_gather_sum<<<grid, 256>>>(buf, idx, out);
}